// round 9
// baseline (speedup 1.0000x reference)
#include <cuda_runtime.h>
#include <cuda_bf16.h>
#include <math.h>
#include <float.h>
#include <stdint.h>

// Problem constants
#define B_     16
#define C_     384
#define HEADS_ 6
#define D_     64
#define N_     1024
#define O3C    1152

__device__ float g_qkv[B_ * O3C * N_];   // tf32-rounded values (GEMM epilogue)
__device__ int g_mask_mode;              // 0 = uint8 bool, 1 = int32, 2 = float32
#define MWORDS (B_ * HEADS_ * N_ * (N_ / 32))
__device__ uint32_t g_mbits[MWORDS];     // bit-packed drop mask

// Pre-split W: hi/lo bf16 pairs, packed as (pc, pc+4) uint2: [ci][o][pc]
#define WPP_N (24 * O3C * 4)
__device__ uint2 g_wpph[WPP_N];
__device__ uint2 g_wppl[WPP_N];

// Packed K/V for attention: per (b,h,chunk): K [32 rp][64 m], V [64 n][32 pc]
#define KPWORDS (B_ * HEADS_ * 16 * 32 * 64)   // 3,145,728 uint2 each
__device__ uint2 g_kp[KPWORDS];
__device__ uint2 g_vp[KPWORDS];

// ---------------------------------------------------------------------------
__device__ __forceinline__ uint32_t f2tf32(float f) {
    uint32_t r;
    asm("cvt.rna.tf32.f32 %0, %1;" : "=r"(r) : "f"(f));
    return r;
}

__device__ __forceinline__ void mma8(float* c, const uint32_t* a,
                                     uint32_t b0, uint32_t b1) {
    asm volatile(
        "mma.sync.aligned.m16n8k8.row.col.f32.tf32.tf32.f32 "
        "{%0,%1,%2,%3}, {%4,%5,%6,%7}, {%8,%9}, {%0,%1,%2,%3};\n"
        : "+f"(c[0]), "+f"(c[1]), "+f"(c[2]), "+f"(c[3])
        : "r"(a[0]), "r"(a[1]), "r"(a[2]), "r"(a[3]), "r"(b0), "r"(b1));
}

__device__ __forceinline__ void mma16(float* c, const uint32_t* a,
                                      uint32_t b0, uint32_t b1) {
    asm volatile(
        "mma.sync.aligned.m16n8k16.row.col.f32.bf16.bf16.f32 "
        "{%0,%1,%2,%3}, {%4,%5,%6,%7}, {%8,%9}, {%0,%1,%2,%3};\n"
        : "+f"(c[0]), "+f"(c[1]), "+f"(c[2]), "+f"(c[3])
        : "r"(a[0]), "r"(a[1]), "r"(a[2]), "r"(a[3]), "r"(b0), "r"(b1));
}

__device__ __forceinline__ uint32_t pack_bf16(float f0, float f1) {
    __nv_bfloat162 t = __floats2bfloat162_rn(f0, f1);
    return *(uint32_t*)&t;
}

__device__ __forceinline__ void cpa16(void* smem, const void* g) {
    uint32_t s = (uint32_t)__cvta_generic_to_shared(smem);
    asm volatile("cp.async.cg.shared.global [%0], [%1], 16;" :: "r"(s), "l"(g));
}

__device__ __forceinline__ float fexp2(float y) {
    y = fmaxf(y, -126.0f);
    float z = y + 12582912.0f;
    int   n = __float_as_int(z) - 0x4B400000;
    float f = y - (z - 12582912.0f);
    float p = 1.3333558146e-3f;
    p = fmaf(p, f, 9.6181291076e-3f);
    p = fmaf(p, f, 5.5504108665e-2f);
    p = fmaf(p, f, 2.4022650696e-1f);
    p = fmaf(p, f, 6.9314718056e-1f);
    p = fmaf(p, f, 1.0f);
    return __int_as_float(__float_as_int(p) + (n << 23));
}

// ---------------------------------------------------------------------------
__global__ void detect_mask_kernel(const uint4* __restrict__ m) {
    __shared__ int s_off4, s_gt1;
    if (threadIdx.x == 0) { s_off4 = 0; s_gt1 = 0; }
    __syncthreads();
    int off4 = 0, gt1 = 0;
    for (int i = threadIdx.x; i < 4096; i += blockDim.x) {
        uint4 v = m[i];
        unsigned a = v.x | v.y | v.z | v.w;
        if (a & 0xFFFFFF00u) off4 = 1;
        if (a & 0xFEFEFEFEu) gt1  = 1;
    }
    if (off4) atomicOr(&s_off4, 1);
    if (gt1)  atomicOr(&s_gt1, 1);
    __syncthreads();
    if (threadIdx.x == 0) g_mask_mode = s_gt1 ? 2 : (s_off4 ? 0 : 1);
}

// ---------------------------------------------------------------------------
#define B4(t) (((t) | ((t) >> 7) | ((t) >> 14) | ((t) >> 21)) & 0xFu)

__global__ void maskpack_kernel(const unsigned char* __restrict__ m) {
    int w = blockIdx.x * blockDim.x + threadIdx.x;
    if (w >= MWORDS) return;
    int mode = g_mask_mode;
    uint32_t bits = 0;
    if (mode == 0) {
        const uint4* p = (const uint4*)m + w * 2;
        uint4 a = p[0], b = p[1];
        bits  = B4(a.x) | (B4(a.y) << 4) | (B4(a.z) << 8)  | (B4(a.w) << 12)
              | (B4(b.x) << 16) | (B4(b.y) << 20) | (B4(b.z) << 24) | (B4(b.w) << 28);
    } else if (mode == 1) {
        const int4* p = (const int4*)m + w * 8;
        #pragma unroll
        for (int i = 0; i < 8; i++) {
            int4 v = p[i];
            bits |= (uint32_t)((v.x != 0) | ((v.y != 0) << 1) |
                               ((v.z != 0) << 2) | ((v.w != 0) << 3)) << (i * 4);
        }
    } else {
        const float4* p = (const float4*)m + w * 8;
        #pragma unroll
        for (int i = 0; i < 8; i++) {
            float4 v = p[i];
            bits |= (uint32_t)((v.x != 0.f) | ((v.y != 0.f) << 1) |
                               ((v.z != 0.f) << 2) | ((v.w != 0.f) << 3)) << (i * 4);
        }
    }
    g_mbits[w] = bits;
}

// ---------------------------------------------------------------------------
// W split + pair-pack: g_wpp[ci][o][pc] = {Whp[o][ci*8+pc], Whp[o][ci*8+pc+4]}
// ---------------------------------------------------------------------------
__global__ void wsplit_kernel(const float* __restrict__ w) {
    int idx = blockIdx.x * blockDim.x + threadIdx.x;
    if (idx >= WPP_N) return;
    int pc = idx & 3;
    int o  = (idx >> 2) % O3C;
    int ci = idx / (4 * O3C);
    int c2a = ci * 8 + pc;
    float2 va = *(const float2*)&w[o * C_ + 2 * c2a];
    float2 vb = *(const float2*)&w[o * C_ + 2 * (c2a + 4)];
    __nv_bfloat16 a0 = __float2bfloat16(va.x), a1 = __float2bfloat16(va.y);
    __nv_bfloat16 b0 = __float2bfloat16(vb.x), b1 = __float2bfloat16(vb.y);
    uint2 hi, lo;
    hi.x = ((uint32_t)*(uint16_t*)&a1 << 16) | *(uint16_t*)&a0;
    hi.y = ((uint32_t)*(uint16_t*)&b1 << 16) | *(uint16_t*)&b0;
    lo.x = pack_bf16(va.x - __bfloat162float(a0), va.y - __bfloat162float(a1));
    lo.y = pack_bf16(vb.x - __bfloat162float(b0), vb.y - __bfloat162float(b1));
    g_wpph[idx] = hi;
    g_wppl[idx] = lo;
}

// ---------------------------------------------------------------------------
// Pack K: g_kp[b][h][kc][rp][m] = {K[d][key], K[d+4][key]}, d=(rp>>2)*8+(rp&3)
// Pack V: g_vp[b][h][kc][n][pc] = {V[n][key], V[n][key+4]}, key=kc*64+(pc>>2)*8+(pc&3)
// ---------------------------------------------------------------------------
__global__ void kpack_kernel() {
    int idx = blockIdx.x * blockDim.x + threadIdx.x;
    if (idx >= KPWORDS) return;
    int m  = idx & 63;
    int rp = (idx >> 6) & 31;
    int kc = (idx >> 11) & 15;
    int t  = idx >> 15;
    int h = t % HEADS_, b = t / HEADS_;
    int d = (rp >> 2) * 8 + (rp & 3);
    int key = kc * 64 + m;
    const float* kb = g_qkv + b * O3C * N_ + (C_ + h * D_) * N_;
    uint2 o;
    o.x = __float_as_uint(kb[d * N_ + key]);
    o.y = __float_as_uint(kb[(d + 4) * N_ + key]);
    g_kp[idx] = o;
}

__global__ void vpack_kernel() {
    int idx = blockIdx.x * blockDim.x + threadIdx.x;
    if (idx >= KPWORDS) return;
    int pc = idx & 31;
    int n  = (idx >> 5) & 63;
    int kc = (idx >> 11) & 15;
    int t  = idx >> 15;
    int h = t % HEADS_, b = t / HEADS_;
    int key = kc * 64 + (pc >> 2) * 8 + (pc & 3);
    const float* vb = g_qkv + b * O3C * N_ + (2 * C_ + h * D_) * N_;
    uint2 o;
    o.x = __float_as_uint(vb[n * N_ + key]);
    o.y = __float_as_uint(vb[n * N_ + key + 4]);
    g_vp[idx] = o;
}

// ---------------------------------------------------------------------------
// QKV GEMM, bf16 hi/lo 3-term, m16n8k16, all frags via LDS.64.
// Tile 128(o) x 128(n), KC=16. 8 warps, warp tile 32(o) x 64(n). grid (8,9,16)
// ---------------------------------------------------------------------------
#define SX2 132
#define NCHUNK (C_ / 16)

__global__ __launch_bounds__(256, 2) void qkv_gemm_kernel(
    const float* __restrict__ x)
{
    __shared__ uint2 Wpph[128 * 4], Wppl[128 * 4];   // stride 4 uint2
    __shared__ uint2 Xpph[4 * SX2], Xppl[4 * SX2];   // stride 132 uint2

    const int b  = blockIdx.z;
    const int o0 = blockIdx.y * 128;
    const int n0 = blockIdx.x * 128;
    const int tid  = threadIdx.x;
    const int wid  = tid >> 5;
    const int lane = tid & 31;
    const int m_base = (wid >> 1) * 32;
    const int n_base = (wid & 1) * 64;
    const int gi = lane >> 2;
    const int ti = lane & 3;

    const float* xb = x + b * C_ * N_;

    // W loader: o row + uint4 half
    const int wo = tid >> 1;
    const int wh2 = (tid & 1) * 2;          // pc offset 0/2 (uint4 = 2 uint2)
    // X loader: tp row (0..3), 2 columns
    const int tp = tid >> 6;
    const int nc = (tid & 63) * 2;

    float acc[2][8][4];
    #pragma unroll
    for (int mf = 0; mf < 2; mf++)
        #pragma unroll
        for (int nf = 0; nf < 8; nf++)
            #pragma unroll
            for (int k = 0; k < 4; k++) acc[mf][nf][k] = 0.f;

    // ---- prefetch chunk 0 ----
    const uint2* wh_p = &g_wpph[(0 * O3C + o0 + wo) * 4 + wh2];
    const uint2* wl_p = &g_wppl[(0 * O3C + o0 + wo) * 4 + wh2];
    const float* xA0 = &xb[(2 * tp) * N_ + n0 + nc];
    uint4  whv = *(const uint4*)wh_p;
    uint4  wlv = *(const uint4*)wl_p;
    float2 ra0 = *(const float2*)xA0;
    float2 ra1 = *(const float2*)(xA0 + N_);
    float2 rb0 = *(const float2*)(xA0 + 8 * N_);
    float2 rb1 = *(const float2*)(xA0 + 9 * N_);

    for (int ci = 0; ci < NCHUNK; ci++) {
        // ---- store current chunk ----
        *(uint4*)&Wpph[wo * 4 + wh2] = whv;
        *(uint4*)&Wppl[wo * 4 + wh2] = wlv;
        {
            __nv_bfloat16 ha0 = __float2bfloat16(ra0.x), ha1 = __float2bfloat16(ra1.x);
            __nv_bfloat16 hb0 = __float2bfloat16(rb0.x), hb1 = __float2bfloat16(rb1.x);
            __nv_bfloat16 ha2 = __float2bfloat16(ra0.y), ha3 = __float2bfloat16(ra1.y);
            __nv_bfloat16 hb2 = __float2bfloat16(rb0.y), hb3 = __float2bfloat16(rb1.y);
            uint4 hv, lv;
            hv.x = ((uint32_t)*(uint16_t*)&ha1 << 16) | *(uint16_t*)&ha0;
            hv.y = ((uint32_t)*(uint16_t*)&hb1 << 16) | *(uint16_t*)&hb0;
            hv.z = ((uint32_t)*(uint16_t*)&ha3 << 16) | *(uint16_t*)&ha2;
            hv.w = ((uint32_t)*(uint16_t*)&hb3 << 16) | *(uint16_t*)&hb2;
            lv.x = pack_bf16(ra0.x - __bfloat162float(ha0), ra1.x - __bfloat162float(ha1));
            lv.y = pack_bf16(rb0.x - __bfloat162float(hb0), rb1.x - __bfloat162float(hb1));
            lv.z = pack_bf16(ra0.y - __bfloat162float(ha2), ra1.y - __bfloat162float(ha3));
            lv.w = pack_bf16(rb0.y - __bfloat162float(hb2), rb1.y - __bfloat162float(hb3));
            *(uint4*)&Xpph[tp * SX2 + nc] = hv;
            *(uint4*)&Xppl[tp * SX2 + nc] = lv;
        }
        __syncthreads();

        // ---- prefetch next ----
        if (ci + 1 < NCHUNK) {
            wh_p += O3C * 4; wl_p += O3C * 4; xA0 += 16 * N_;
            whv = *(const uint4*)wh_p;
            wlv = *(const uint4*)wl_p;
            ra0 = *(const float2*)xA0;
            ra1 = *(const float2*)(xA0 + N_);
            rb0 = *(const float2*)(xA0 + 8 * N_);
            rb1 = *(const float2*)(xA0 + 9 * N_);
        }

        // ---- A frags: 2 LDS.64 per mf per hi/lo ----
        uint32_t ah[2][4], al[2][4];
        #pragma unroll
        for (int mf = 0; mf < 2; mf++) {
            int r = m_base + mf * 16 + gi;
            uint2 u0 = Wpph[r * 4 + ti];
            uint2 u1 = Wpph[(r + 8) * 4 + ti];
            ah[mf][0] = u0.x; ah[mf][1] = u1.x; ah[mf][2] = u0.y; ah[mf][3] = u1.y;
            uint2 v0 = Wppl[r * 4 + ti];
            uint2 v1 = Wppl[(r + 8) * 4 + ti];
            al[mf][0] = v0.x; al[mf][1] = v1.x; al[mf][2] = v0.y; al[mf][3] = v1.y;
        }
        #pragma unroll
        for (int nf = 0; nf < 8; nf++) {
            int col = n_base + nf * 8 + gi;
            uint2 bh = Xpph[ti * SX2 + col];
            uint2 bl = Xppl[ti * SX2 + col];
            #pragma unroll
            for (int mf = 0; mf < 2; mf++) {
                mma16(acc[mf][nf], ah[mf], bh.x, bh.y);
                mma16(acc[mf][nf], ah[mf], bl.x, bl.y);
                mma16(acc[mf][nf], al[mf], bh.x, bh.y);
            }
        }
        __syncthreads();
    }

    // Epilogue: round to tf32 so downstream copies are conversion-free.
    float* outb = g_qkv + b * O3C * N_;
    #pragma unroll
    for (int mf = 0; mf < 2; mf++) {
        int r = o0 + m_base + mf * 16 + gi;
        #pragma unroll
        for (int nf = 0; nf < 8; nf++) {
            int nc2 = n0 + n_base + nf * 8 + 2 * ti;
            *(float2*)&outb[r * N_ + nc2] = make_float2(
                __uint_as_float(f2tf32(acc[mf][nf][0])),
                __uint_as_float(f2tf32(acc[mf][nf][1])));
            *(float2*)&outb[(r + 8) * N_ + nc2] = make_float2(
                __uint_as_float(f2tf32(acc[mf][nf][2])),
                __uint_as_float(f2tf32(acc[mf][nf][3])));
        }
    }
}

// ---------------------------------------------------------------------------
// Fused flash attention: packed K/V (LDS.64 frags), cp.async double buffer,
// bit-mask. 128 q rows, 8 warps. grid (8, 6, 16)
// ---------------------------------------------------------------------------
#define AST 68
#define QP_OFF  0
#define KP0_OFF (128 * AST)               // 8704 (words)
#define VP0_OFF (KP0_OFF + 32 * 68 * 2)   // +4352 = 13056
#define KP1_OFF (VP0_OFF + 64 * 36 * 2)   // +4608 = 17664
#define VP1_OFF (KP1_OFF + 32 * 68 * 2)   // 22016
#define SMEM_WORDS (VP1_OFF + 64 * 36 * 2) // 26624
#define ATTN_SMEM (SMEM_WORDS * 4)         // 106496 B

__global__ __launch_bounds__(256, 2) void attn_kernel(float* __restrict__ out)
{
    extern __shared__ uint32_t As[];
    uint32_t* QP = As;                       // [128][AST]  Q then P

    const int q0 = blockIdx.x * 128;
    const int h  = blockIdx.y;
    const int b  = blockIdx.z;
    const int tid  = threadIdx.x;
    const int wid  = tid >> 5;
    const int lane = tid & 31;
    const int gi = lane >> 2;
    const int ti = lane & 3;
    const int wq = wid * 16;

    const float sc2 = rsqrtf((float)C_) * 1.4426950408889634f;
    const float NEG = -1e30f;

    const float* qb = g_qkv + (b * O3C + h * D_) * N_;
    const int bh16 = (b * HEADS_ + h) * 16;
    const int mbase = (b * HEADS_ + h) * N_ * N_;

    auto fill = [&](int sel, int kc) {
        uint2* Kb = (uint2*)(As + (sel ? KP1_OFF : KP0_OFF));
        uint2* Vb = (uint2*)(As + (sel ? VP1_OFF : VP0_OFF));
        const uint2* kg = g_kp + ((size_t)(bh16 + kc) << 11);
        const uint2* vg = g_vp + ((size_t)(bh16 + kc) << 11);
        #pragma unroll
        for (int i = 0; i < 4; i++) {
            int e = tid + i * 256;
            int kr = e >> 5, kcp = (e & 31) * 2;
            cpa16(&Kb[kr * 68 + kcp], &kg[kr * 64 + kcp]);
            int vr = e >> 4, vcp = (e & 15) * 2;
            cpa16(&Vb[vr * 36 + vcp], &vg[vr * 32 + vcp]);
        }
        asm volatile("cp.async.commit_group;" ::: "memory");
    };

    fill(0, 0);

    // ---- Stage Q tile (already tf32; raw copy, transposed) ----
    for (int e = tid; e < 64 * 32; e += 256) {
        int dd = e >> 5, q4 = (e & 31) * 4;
        uint4 v = *(const uint4*)&qb[dd * N_ + q0 + q4];
        QP[(q4 + 0) * AST + dd] = v.x;
        QP[(q4 + 1) * AST + dd] = v.y;
        QP[(q4 + 2) * AST + dd] = v.z;
        QP[(q4 + 3) * AST + dd] = v.w;
    }
    __syncthreads();

    uint32_t qa[8][4];
    #pragma unroll
    for (int ks = 0; ks < 8; ks++) {
        int r = wq + gi, c = ks * 8 + ti;
        qa[ks][0] = QP[r * AST + c];
        qa[ks][1] = QP[(r + 8) * AST + c];
        qa[ks][2] = QP[r * AST + c + 4];
        qa[ks][3] = QP[(r + 8) * AST + c + 4];
    }
    __syncthreads();

    float oa[8][4];
    #pragma unroll
    for (int nf = 0; nf < 8; nf++)
        #pragma unroll
        for (int k = 0; k < 4; k++) oa[nf][k] = 0.f;
    float m1 = NEG, m2 = NEG, l1 = 0.f, l2 = 0.f;

    const int r1g = q0 + wq + gi;
    const int mrow = (mbase + r1g * N_) >> 5;

    for (int kc = 0; kc < 16; kc++) {
        asm volatile("cp.async.wait_group 0;" ::: "memory");
        __syncthreads();

        const int widx = mrow + kc * 2;
        uint2 mwa = *(const uint2*)&g_mbits[widx];
        uint2 mwc = *(const uint2*)&g_mbits[widx + 256];

        if (kc + 1 < 16) fill((kc + 1) & 1, kc + 1);

        const uint2* Kp = (const uint2*)(As + ((kc & 1) ? KP1_OFF : KP0_OFF));
        const uint2* Vp = (const uint2*)(As + ((kc & 1) ? VP1_OFF : VP0_OFF));

        // ---- S = Q K^T : B-frags one LDS.64 each ----
        float sa[8][4];
        #pragma unroll
        for (int nf = 0; nf < 8; nf++)
            #pragma unroll
            for (int k = 0; k < 4; k++) sa[nf][k] = 0.f;
        #pragma unroll
        for (int ks = 0; ks < 8; ks++) {
            const uint2* krow = &Kp[(ks * 4 + ti) * 68 + gi];
            #pragma unroll
            for (int nf = 0; nf < 8; nf++) {
                uint2 bb = krow[nf * 8];
                mma8(sa[nf], qa[ks], bb.x, bb.y);
            }
        }

        // ---- scale + mask ----
        #pragma unroll
        for (int nf = 0; nf < 8; nf++) {
            uint32_t wa = (nf < 4) ? mwa.x : mwa.y;
            uint32_t wc = (nf < 4) ? mwc.x : mwc.y;
            int sh = (nf & 3) * 8 + 2 * ti;
            sa[nf][0] = ((wa >> sh) & 1)       ? NEG : sa[nf][0] * sc2;
            sa[nf][1] = ((wa >> (sh + 1)) & 1) ? NEG : sa[nf][1] * sc2;
            sa[nf][2] = ((wc >> sh) & 1)       ? NEG : sa[nf][2] * sc2;
            sa[nf][3] = ((wc >> (sh + 1)) & 1) ? NEG : sa[nf][3] * sc2;
        }

        // ---- online softmax ----
        float mx1 = NEG, mx2 = NEG;
        #pragma unroll
        for (int nf = 0; nf < 8; nf++) {
            mx1 = fmaxf(mx1, fmaxf(sa[nf][0], sa[nf][1]));
            mx2 = fmaxf(mx2, fmaxf(sa[nf][2], sa[nf][3]));
        }
        mx1 = fmaxf(mx1, __shfl_xor_sync(0xffffffffu, mx1, 1));
        mx1 = fmaxf(mx1, __shfl_xor_sync(0xffffffffu, mx1, 2));
        mx2 = fmaxf(mx2, __shfl_xor_sync(0xffffffffu, mx2, 1));
        mx2 = fmaxf(mx2, __shfl_xor_sync(0xffffffffu, mx2, 2));
        float mn1 = fmaxf(m1, mx1), mn2 = fmaxf(m2, mx2);
        float corr1 = fexp2(m1 - mn1), corr2 = fexp2(m2 - mn2);

        float ls1 = 0.f, ls2 = 0.f;
        #pragma unroll
        for (int nf = 0; nf < 8; nf++) {
            float p00 = fexp2(sa[nf][0] - mn1);
            float p01 = fexp2(sa[nf][1] - mn1);
            float p10 = fexp2(sa[nf][2] - mn2);
            float p11 = fexp2(sa[nf][3] - mn2);
            ls1 += p00 + p01;
            ls2 += p10 + p11;
            int col = nf * 8 + 2 * ti;
            QP[(wq + gi) * AST + col]         = f2tf32(p00);
            QP[(wq + gi) * AST + col + 1]     = f2tf32(p01);
            QP[(wq + gi + 8) * AST + col]     = f2tf32(p10);
            QP[(wq + gi + 8) * AST + col + 1] = f2tf32(p11);
        }
        ls1 += __shfl_xor_sync(0xffffffffu, ls1, 1);
        ls1 += __shfl_xor_sync(0xffffffffu, ls1, 2);
        ls2 += __shfl_xor_sync(0xffffffffu, ls2, 1);
        ls2 += __shfl_xor_sync(0xffffffffu, ls2, 2);
        l1 = l1 * corr1 + ls1;
        l2 = l2 * corr2 + ls2;
        m1 = mn1; m2 = mn2;
        #pragma unroll
        for (int nf = 0; nf < 8; nf++) {
            oa[nf][0] *= corr1; oa[nf][1] *= corr1;
            oa[nf][2] *= corr2; oa[nf][3] *= corr2;
        }
        __syncwarp();

        // ---- O += P V : V frags one LDS.64 each ----
        #pragma unroll
        for (int kf = 0; kf < 8; kf++) {
            uint32_t pa[4];
            int r = wq + gi, c = kf * 8 + ti;
            pa[0] = QP[r * AST + c];
            pa[1] = QP[(r + 8) * AST + c];
            pa[2] = QP[r * AST + c + 4];
            pa[3] = QP[(r + 8) * AST + c + 4];
            const uint2* vrow = &Vp[gi * 36 + kf * 4 + ti];
            #pragma unroll
            for (int nf = 0; nf < 8; nf++) {
                uint2 vv = vrow[nf * 8 * 36];
                mma8(oa[nf], pa, vv.x, vv.y);
            }
        }
    }
    __syncthreads();

    // ---- normalize + stage to smem [d][q] for coalesced output ----
    float* Od = (float*)(As + KP0_OFF);   // overlays buffers
    float il1 = 1.0f / l1, il2 = 1.0f / l2;
    #pragma unroll
    for (int nf = 0; nf < 8; nf++) {
        int d0 = nf * 8 + 2 * ti;
        Od[d0 * 132 + wq + gi]           = oa[nf][0] * il1;
        Od[(d0 + 1) * 132 + wq + gi]     = oa[nf][1] * il1;
        Od[d0 * 132 + wq + gi + 8]       = oa[nf][2] * il2;
        Od[(d0 + 1) * 132 + wq + gi + 8] = oa[nf][3] * il2;
    }
    __syncthreads();

    float* ob = out + (b * C_ + h * D_) * N_;
    for (int e = tid; e < 64 * 32; e += 256) {
        int dd = e >> 5, q4 = (e & 31) * 4;
        *(float4*)&ob[dd * N_ + q0 + q4] = *(const float4*)&Od[dd * 132 + q4];
    }
}

// ---------------------------------------------------------------------------
extern "C" void kernel_launch(void* const* d_in, const int* in_sizes, int n_in,
                              void* d_out, int out_size)
{
    const float* x         = (const float*)d_in[0];
    const float* w_qkv     = (const float*)d_in[1];
    const unsigned char* m = (const unsigned char*)d_in[2];
    float* out             = (float*)d_out;

    cudaFuncSetAttribute(attn_kernel,
                         cudaFuncAttributeMaxDynamicSharedMemorySize, ATTN_SMEM);

    detect_mask_kernel<<<1, 1024>>>((const uint4*)m);
    maskpack_kernel<<<MWORDS / 256, 256>>>(m);
    wsplit_kernel<<<(WPP_N + 255) / 256, 256>>>(w_qkv);

    dim3 gemm_grid(N_ / 128, O3C / 128, B_);   // (8, 9, 16)
    qkv_gemm_kernel<<<gemm_grid, 256>>>(x);

    kpack_kernel<<<KPWORDS / 256, 256>>>();
    vpack_kernel<<<KPWORDS / 256, 256>>>();

    dim3 attn_grid(N_ / 128, HEADS_, B_);      // (8, 6, 16)
    attn_kernel<<<attn_grid, 256, ATTN_SMEM>>>(out);
}

// round 10
// speedup vs baseline: 1.0037x; 1.0037x over previous
#include <cuda_runtime.h>
#include <cuda_bf16.h>
#include <math.h>
#include <float.h>
#include <stdint.h>

// Problem constants
#define B_     16
#define C_     384
#define HEADS_ 6
#define D_     64
#define N_     1024
#define O3C    1152
#define C2     (C_ / 2)      // 192

__device__ float g_qkv[B_ * O3C * N_];   // tf32-rounded values (GEMM epilogue)
__device__ int g_mask_mode;              // 0 = uint8 bool, 1 = int32, 2 = float32
#define MWORDS (B_ * HEADS_ * N_ * (N_ / 32))
__device__ uint32_t g_mbits[MWORDS];     // bit-packed drop mask

// Pre-split W: hi/lo bf16 k-pairs, [o][c2]
__device__ uint32_t g_wh[O3C * C2];
__device__ uint32_t g_wl[O3C * C2];
// Pre-split X: hi/lo bf16 vertical k-pairs, [b][c2][n]
__device__ uint32_t g_xh[B_ * C2 * N_];
__device__ uint32_t g_xl[B_ * C2 * N_];

// ---------------------------------------------------------------------------
__device__ __forceinline__ uint32_t f2tf32(float f) {
    uint32_t r;
    asm("cvt.rna.tf32.f32 %0, %1;" : "=r"(r) : "f"(f));
    return r;
}

__device__ __forceinline__ void mma8(float* c, const uint32_t* a,
                                     uint32_t b0, uint32_t b1) {
    asm volatile(
        "mma.sync.aligned.m16n8k8.row.col.f32.tf32.tf32.f32 "
        "{%0,%1,%2,%3}, {%4,%5,%6,%7}, {%8,%9}, {%0,%1,%2,%3};\n"
        : "+f"(c[0]), "+f"(c[1]), "+f"(c[2]), "+f"(c[3])
        : "r"(a[0]), "r"(a[1]), "r"(a[2]), "r"(a[3]), "r"(b0), "r"(b1));
}

__device__ __forceinline__ void mma16(float* c, const uint32_t* a,
                                      uint32_t b0, uint32_t b1) {
    asm volatile(
        "mma.sync.aligned.m16n8k16.row.col.f32.bf16.bf16.f32 "
        "{%0,%1,%2,%3}, {%4,%5,%6,%7}, {%8,%9}, {%0,%1,%2,%3};\n"
        : "+f"(c[0]), "+f"(c[1]), "+f"(c[2]), "+f"(c[3])
        : "r"(a[0]), "r"(a[1]), "r"(a[2]), "r"(a[3]), "r"(b0), "r"(b1));
}

__device__ __forceinline__ uint32_t pack_bf16(float f0, float f1) {
    __nv_bfloat162 t = __floats2bfloat162_rn(f0, f1);
    return *(uint32_t*)&t;
}

__device__ __forceinline__ void cpa16(void* smem, const void* g) {
    uint32_t s = (uint32_t)__cvta_generic_to_shared(smem);
    asm volatile("cp.async.cg.shared.global [%0], [%1], 16;" :: "r"(s), "l"(g));
}

__device__ __forceinline__ float fexp2(float y) {
    y = fmaxf(y, -126.0f);
    float z = y + 12582912.0f;
    int   n = __float_as_int(z) - 0x4B400000;
    float f = y - (z - 12582912.0f);
    float p = 1.3333558146e-3f;
    p = fmaf(p, f, 9.6181291076e-3f);
    p = fmaf(p, f, 5.5504108665e-2f);
    p = fmaf(p, f, 2.4022650696e-1f);
    p = fmaf(p, f, 6.9314718056e-1f);
    p = fmaf(p, f, 1.0f);
    return __int_as_float(__float_as_int(p) + (n << 23));
}

// ---------------------------------------------------------------------------
__global__ void detect_mask_kernel(const uint4* __restrict__ m) {
    __shared__ int s_off4, s_gt1;
    if (threadIdx.x == 0) { s_off4 = 0; s_gt1 = 0; }
    __syncthreads();
    int off4 = 0, gt1 = 0;
    for (int i = threadIdx.x; i < 4096; i += blockDim.x) {
        uint4 v = m[i];
        unsigned a = v.x | v.y | v.z | v.w;
        if (a & 0xFFFFFF00u) off4 = 1;
        if (a & 0xFEFEFEFEu) gt1  = 1;
    }
    if (off4) atomicOr(&s_off4, 1);
    if (gt1)  atomicOr(&s_gt1, 1);
    __syncthreads();
    if (threadIdx.x == 0) g_mask_mode = s_gt1 ? 2 : (s_off4 ? 0 : 1);
}

// ---------------------------------------------------------------------------
#define B4(t) (((t) | ((t) >> 7) | ((t) >> 14) | ((t) >> 21)) & 0xFu)

__global__ void maskpack_kernel(const unsigned char* __restrict__ m) {
    int w = blockIdx.x * blockDim.x + threadIdx.x;
    if (w >= MWORDS) return;
    int mode = g_mask_mode;
    uint32_t bits = 0;
    if (mode == 0) {
        const uint4* p = (const uint4*)m + w * 2;
        uint4 a = p[0], b = p[1];
        bits  = B4(a.x) | (B4(a.y) << 4) | (B4(a.z) << 8)  | (B4(a.w) << 12)
              | (B4(b.x) << 16) | (B4(b.y) << 20) | (B4(b.z) << 24) | (B4(b.w) << 28);
    } else if (mode == 1) {
        const int4* p = (const int4*)m + w * 8;
        #pragma unroll
        for (int i = 0; i < 8; i++) {
            int4 v = p[i];
            bits |= (uint32_t)((v.x != 0) | ((v.y != 0) << 1) |
                               ((v.z != 0) << 2) | ((v.w != 0) << 3)) << (i * 4);
        }
    } else {
        const float4* p = (const float4*)m + w * 8;
        #pragma unroll
        for (int i = 0; i < 8; i++) {
            float4 v = p[i];
            bits |= (uint32_t)((v.x != 0.f) | ((v.y != 0.f) << 1) |
                               ((v.z != 0.f) << 2) | ((v.w != 0.f) << 3)) << (i * 4);
        }
    }
    g_mbits[w] = bits;
}

// ---------------------------------------------------------------------------
// W split (horizontal k-pairs): g_wh[o][j] = pack(w[o][2j], w[o][2j+1])
// ---------------------------------------------------------------------------
__global__ void wsplit_kernel(const float* __restrict__ w) {
    int idx = blockIdx.x * blockDim.x + threadIdx.x;
    if (idx >= O3C * C2) return;
    float2 v = *(const float2*)&w[idx * 2];
    __nv_bfloat16 h0 = __float2bfloat16(v.x);
    __nv_bfloat16 h1 = __float2bfloat16(v.y);
    g_wh[idx] = ((uint32_t)*(uint16_t*)&h1 << 16) | *(uint16_t*)&h0;
    g_wl[idx] = pack_bf16(v.x - __bfloat162float(h0),
                          v.y - __bfloat162float(h1));
}

// ---------------------------------------------------------------------------
// X split (vertical k-pairs): g_xh[b][c2][n] = pack(x[b][2c2][n], x[b][2c2+1][n])
// ---------------------------------------------------------------------------
__global__ void xsplit_kernel(const float* __restrict__ x) {
    int idx = blockIdx.x * blockDim.x + threadIdx.x;
    if (idx >= B_ * C2 * N_) return;
    int n  = idx & (N_ - 1);
    int c2 = (idx >> 10) % C2;
    int b  = idx / (C2 * N_);
    const float* xp = &x[(b * C_ + 2 * c2) * N_ + n];
    float v0 = xp[0], v1 = xp[N_];
    __nv_bfloat16 h0 = __float2bfloat16(v0);
    __nv_bfloat16 h1 = __float2bfloat16(v1);
    g_xh[idx] = ((uint32_t)*(uint16_t*)&h1 << 16) | *(uint16_t*)&h0;
    g_xl[idx] = pack_bf16(v0 - __bfloat162float(h0),
                          v1 - __bfloat162float(h1));
}

// ---------------------------------------------------------------------------
// QKV GEMM: pure cp.async copy + mma16 (no in-kernel conversion).
// Tile 128(o) x 128(n), KC=16, double-buffered. 8 warps, warp 32x64.
// grid = (8, 9, 16). Dynamic smem, 2 stages.
// ---------------------------------------------------------------------------
#define WPST 12
#define XPST 136
#define GW_WH 0
#define GW_WL (128 * WPST)                 // 1536
#define GW_XH (2 * 128 * WPST)             // 3072
#define GW_XL (GW_XH + 8 * XPST)           // 4160
#define G_STG (GW_XL + 8 * XPST)           // 5248 words/stage
#define GEMM_SMEM (2 * G_STG * 4)          // 41984 B
#define NCHUNK (C_ / 16)

__global__ __launch_bounds__(256, 2) void qkv_gemm_kernel()
{
    extern __shared__ uint32_t Sg[];

    const int b  = blockIdx.z;
    const int o0 = blockIdx.y * 128;
    const int n0 = blockIdx.x * 128;
    const int tid  = threadIdx.x;
    const int wid  = tid >> 5;
    const int lane = tid & 31;
    const int m_base = (wid >> 1) * 32;
    const int n_base = (wid & 1) * 64;
    const int gi = lane >> 2;
    const int ti = lane & 3;

    // loader indices
    const int wrow = tid >> 1;              // 0..127
    const int wh4  = (tid & 1) * 4;         // word offset 0/4
    const int xc2  = tid >> 5;              // 0..7
    const int xn4  = (tid & 31) * 4;        // word offset in n

    const uint32_t* whg = &g_wh[(o0 + wrow) * C2 + wh4];
    const uint32_t* wlg = &g_wl[(o0 + wrow) * C2 + wh4];
    const uint32_t* xhg = &g_xh[(b * C2 + xc2) * N_ + n0 + xn4];
    const uint32_t* xlg = &g_xl[(b * C2 + xc2) * N_ + n0 + xn4];

    auto gfill = [&](int sel, int ci) {
        uint32_t* S = Sg + sel * G_STG;
        cpa16(&S[GW_WH + wrow * WPST + wh4], whg + ci * 8);
        cpa16(&S[GW_WL + wrow * WPST + wh4], wlg + ci * 8);
        cpa16(&S[GW_XH + xc2 * XPST + xn4], xhg + ci * 8 * N_);
        cpa16(&S[GW_XL + xc2 * XPST + xn4], xlg + ci * 8 * N_);
        asm volatile("cp.async.commit_group;" ::: "memory");
    };

    float acc[2][8][4];
    #pragma unroll
    for (int mf = 0; mf < 2; mf++)
        #pragma unroll
        for (int nf = 0; nf < 8; nf++)
            #pragma unroll
            for (int k = 0; k < 4; k++) acc[mf][nf][k] = 0.f;

    gfill(0, 0);

    for (int ci = 0; ci < NCHUNK; ci++) {
        asm volatile("cp.async.wait_group 0;" ::: "memory");
        __syncthreads();

        if (ci + 1 < NCHUNK) gfill((ci + 1) & 1, ci + 1);

        const uint32_t* Whp = Sg + ((ci & 1) ? G_STG : 0) + GW_WH;
        const uint32_t* Wlp = Whp + GW_WL;
        const uint32_t* Xhp = Whp + GW_XH - GW_WH;
        const uint32_t* Xlp = Whp + GW_XL - GW_WH;

        uint32_t ah[2][4], al[2][4];
        #pragma unroll
        for (int mf = 0; mf < 2; mf++) {
            int r = m_base + mf * 16 + gi;
            ah[mf][0] = Whp[r * WPST + ti];
            ah[mf][1] = Whp[(r + 8) * WPST + ti];
            ah[mf][2] = Whp[r * WPST + ti + 4];
            ah[mf][3] = Whp[(r + 8) * WPST + ti + 4];
            al[mf][0] = Wlp[r * WPST + ti];
            al[mf][1] = Wlp[(r + 8) * WPST + ti];
            al[mf][2] = Wlp[r * WPST + ti + 4];
            al[mf][3] = Wlp[(r + 8) * WPST + ti + 4];
        }
        #pragma unroll
        for (int nf = 0; nf < 8; nf++) {
            int col = n_base + nf * 8 + gi;
            uint32_t bh0 = Xhp[ti * XPST + col];
            uint32_t bh1 = Xhp[(ti + 4) * XPST + col];
            uint32_t bl0 = Xlp[ti * XPST + col];
            uint32_t bl1 = Xlp[(ti + 4) * XPST + col];
            #pragma unroll
            for (int mf = 0; mf < 2; mf++) {
                mma16(acc[mf][nf], ah[mf], bh0, bh1);
                mma16(acc[mf][nf], ah[mf], bl0, bl1);
                mma16(acc[mf][nf], al[mf], bh0, bh1);
            }
        }
        // next iteration's wait+sync protects buffer reuse
    }

    // Epilogue: round to tf32 so attention copies raw.
    float* outb = g_qkv + b * O3C * N_;
    #pragma unroll
    for (int mf = 0; mf < 2; mf++) {
        int r = o0 + m_base + mf * 16 + gi;
        #pragma unroll
        for (int nf = 0; nf < 8; nf++) {
            int nc2 = n0 + n_base + nf * 8 + 2 * ti;
            *(float2*)&outb[r * N_ + nc2] = make_float2(
                __uint_as_float(f2tf32(acc[mf][nf][0])),
                __uint_as_float(f2tf32(acc[mf][nf][1])));
            *(float2*)&outb[(r + 8) * N_ + nc2] = make_float2(
                __uint_as_float(f2tf32(acc[mf][nf][2])),
                __uint_as_float(f2tf32(acc[mf][nf][3])));
        }
    }
}

// ---------------------------------------------------------------------------
// Fused flash attention (R7 verbatim): raw tf32 Q/K/V, cp.async double buffer,
// bit-packed mask. 128 q rows, 8 warps. grid (8, 6, 16)
// ---------------------------------------------------------------------------
#define AST 68
#define KST 72
#define K0_OFF (128 * AST)            // 8704
#define V0_OFF (K0_OFF + 64 * KST)    // 13312
#define K1_OFF (V0_OFF + 64 * AST)    // 17664
#define V1_OFF (K1_OFF + 64 * KST)    // 22272
#define SMEM_WORDS (V1_OFF + 64 * AST) // 26624
#define ATTN_SMEM (SMEM_WORDS * 4)     // 106496 B

__global__ __launch_bounds__(256, 2) void attn_kernel(float* __restrict__ out)
{
    extern __shared__ uint32_t As[];
    uint32_t* QP = As;                       // [128][AST]  Q then P

    const int q0 = blockIdx.x * 128;
    const int h  = blockIdx.y;
    const int b  = blockIdx.z;
    const int tid  = threadIdx.x;
    const int wid  = tid >> 5;
    const int lane = tid & 31;
    const int gi = lane >> 2;
    const int ti = lane & 3;
    const int wq = wid * 16;

    const float sc2 = rsqrtf((float)C_) * 1.4426950408889634f;
    const float NEG = -1e30f;

    const float* qb = g_qkv + (b * O3C + h * D_) * N_;
    const float* kb = qb + C_ * N_;
    const float* vb = qb + 2 * C_ * N_;

    const int mbase = (b * HEADS_ + h) * N_ * N_;

    auto fill = [&](int sel, int k0) {
        uint32_t* Kb = As + (sel ? K1_OFF : K0_OFF);
        uint32_t* Vb = As + (sel ? V1_OFF : V0_OFF);
        #pragma unroll
        for (int i = 0; i < 4; i++) {
            int e = tid + i * 256;
            int dd = e >> 4, m4 = (e & 15) * 4;
            cpa16(&Kb[dd * KST + m4], &kb[dd * N_ + k0 + m4]);
            cpa16(&Vb[dd * AST + m4], &vb[dd * N_ + k0 + m4]);
        }
        asm volatile("cp.async.commit_group;" ::: "memory");
    };

    fill(0, 0);

    // ---- Stage Q tile (already tf32; raw copy, transposed) ----
    for (int e = tid; e < 64 * 32; e += 256) {
        int dd = e >> 5, q4 = (e & 31) * 4;
        uint4 v = *(const uint4*)&qb[dd * N_ + q0 + q4];
        QP[(q4 + 0) * AST + dd] = v.x;
        QP[(q4 + 1) * AST + dd] = v.y;
        QP[(q4 + 2) * AST + dd] = v.z;
        QP[(q4 + 3) * AST + dd] = v.w;
    }
    __syncthreads();

    uint32_t qa[8][4];
    #pragma unroll
    for (int ks = 0; ks < 8; ks++) {
        int r = wq + gi, c = ks * 8 + ti;
        qa[ks][0] = QP[r * AST + c];
        qa[ks][1] = QP[(r + 8) * AST + c];
        qa[ks][2] = QP[r * AST + c + 4];
        qa[ks][3] = QP[(r + 8) * AST + c + 4];
    }
    __syncthreads();

    float oa[8][4];
    #pragma unroll
    for (int nf = 0; nf < 8; nf++)
        #pragma unroll
        for (int k = 0; k < 4; k++) oa[nf][k] = 0.f;
    float m1 = NEG, m2 = NEG, l1 = 0.f, l2 = 0.f;

    const int r1g = q0 + wq + gi;
    const int mrow = (mbase + r1g * N_) >> 5;

    for (int kc = 0; kc < 16; kc++) {
        const int k0 = kc * 64;
        asm volatile("cp.async.wait_group 0;" ::: "memory");
        __syncthreads();

        const int widx = mrow + (k0 >> 5);
        uint2 mwa = *(const uint2*)&g_mbits[widx];
        uint2 mwc = *(const uint2*)&g_mbits[widx + 256];

        if (kc + 1 < 16) fill((kc + 1) & 1, k0 + 64);

        const uint32_t* Kc = As + ((kc & 1) ? K1_OFF : K0_OFF);
        const uint32_t* Vc = As + ((kc & 1) ? V1_OFF : V0_OFF);

        float sa[8][4];
        #pragma unroll
        for (int nf = 0; nf < 8; nf++)
            #pragma unroll
            for (int k = 0; k < 4; k++) sa[nf][k] = 0.f;
        #pragma unroll
        for (int ks = 0; ks < 8; ks++) {
            #pragma unroll
            for (int nf = 0; nf < 8; nf++) {
                uint32_t b0 = Kc[(ks * 8 + ti) * KST + nf * 8 + gi];
                uint32_t b1 = Kc[(ks * 8 + ti + 4) * KST + nf * 8 + gi];
                mma8(sa[nf], qa[ks], b0, b1);
            }
        }

        #pragma unroll
        for (int nf = 0; nf < 8; nf++) {
            uint32_t wa = (nf < 4) ? mwa.x : mwa.y;
            uint32_t wc = (nf < 4) ? mwc.x : mwc.y;
            int sh = (nf & 3) * 8 + 2 * ti;
            sa[nf][0] = ((wa >> sh) & 1)       ? NEG : sa[nf][0] * sc2;
            sa[nf][1] = ((wa >> (sh + 1)) & 1) ? NEG : sa[nf][1] * sc2;
            sa[nf][2] = ((wc >> sh) & 1)       ? NEG : sa[nf][2] * sc2;
            sa[nf][3] = ((wc >> (sh + 1)) & 1) ? NEG : sa[nf][3] * sc2;
        }

        float mx1 = NEG, mx2 = NEG;
        #pragma unroll
        for (int nf = 0; nf < 8; nf++) {
            mx1 = fmaxf(mx1, fmaxf(sa[nf][0], sa[nf][1]));
            mx2 = fmaxf(mx2, fmaxf(sa[nf][2], sa[nf][3]));
        }
        mx1 = fmaxf(mx1, __shfl_xor_sync(0xffffffffu, mx1, 1));
        mx1 = fmaxf(mx1, __shfl_xor_sync(0xffffffffu, mx1, 2));
        mx2 = fmaxf(mx2, __shfl_xor_sync(0xffffffffu, mx2, 1));
        mx2 = fmaxf(mx2, __shfl_xor_sync(0xffffffffu, mx2, 2));
        float mn1 = fmaxf(m1, mx1), mn2 = fmaxf(m2, mx2);
        float corr1 = fexp2(m1 - mn1), corr2 = fexp2(m2 - mn2);

        float ls1 = 0.f, ls2 = 0.f;
        #pragma unroll
        for (int nf = 0; nf < 8; nf++) {
            float p00 = fexp2(sa[nf][0] - mn1);
            float p01 = fexp2(sa[nf][1] - mn1);
            float p10 = fexp2(sa[nf][2] - mn2);
            float p11 = fexp2(sa[nf][3] - mn2);
            ls1 += p00 + p01;
            ls2 += p10 + p11;
            int col = nf * 8 + 2 * ti;
            QP[(wq + gi) * AST + col]         = f2tf32(p00);
            QP[(wq + gi) * AST + col + 1]     = f2tf32(p01);
            QP[(wq + gi + 8) * AST + col]     = f2tf32(p10);
            QP[(wq + gi + 8) * AST + col + 1] = f2tf32(p11);
        }
        ls1 += __shfl_xor_sync(0xffffffffu, ls1, 1);
        ls1 += __shfl_xor_sync(0xffffffffu, ls1, 2);
        ls2 += __shfl_xor_sync(0xffffffffu, ls2, 1);
        ls2 += __shfl_xor_sync(0xffffffffu, ls2, 2);
        l1 = l1 * corr1 + ls1;
        l2 = l2 * corr2 + ls2;
        m1 = mn1; m2 = mn2;
        #pragma unroll
        for (int nf = 0; nf < 8; nf++) {
            oa[nf][0] *= corr1; oa[nf][1] *= corr1;
            oa[nf][2] *= corr2; oa[nf][3] *= corr2;
        }
        __syncwarp();

        #pragma unroll
        for (int kf = 0; kf < 8; kf++) {
            uint32_t pa[4];
            int r = wq + gi, c = kf * 8 + ti;
            pa[0] = QP[r * AST + c];
            pa[1] = QP[(r + 8) * AST + c];
            pa[2] = QP[r * AST + c + 4];
            pa[3] = QP[(r + 8) * AST + c + 4];
            #pragma unroll
            for (int nf = 0; nf < 8; nf++) {
                uint32_t b0 = Vc[(nf * 8 + gi) * AST + kf * 8 + ti];
                uint32_t b1 = Vc[(nf * 8 + gi) * AST + kf * 8 + ti + 4];
                mma8(oa[nf], pa, b0, b1);
            }
        }
    }
    __syncthreads();

    float* Od = (float*)(As + K0_OFF);   // [64][132] staging (overlays buffers)
    float il1 = 1.0f / l1, il2 = 1.0f / l2;
    #pragma unroll
    for (int nf = 0; nf < 8; nf++) {
        int d0 = nf * 8 + 2 * ti;
        Od[d0 * 132 + wq + gi]           = oa[nf][0] * il1;
        Od[(d0 + 1) * 132 + wq + gi]     = oa[nf][1] * il1;
        Od[d0 * 132 + wq + gi + 8]       = oa[nf][2] * il2;
        Od[(d0 + 1) * 132 + wq + gi + 8] = oa[nf][3] * il2;
    }
    __syncthreads();

    float* ob = out + (b * C_ + h * D_) * N_;
    for (int e = tid; e < 64 * 32; e += 256) {
        int dd = e >> 5, q4 = (e & 31) * 4;
        *(float4*)&ob[dd * N_ + q0 + q4] = *(const float4*)&Od[dd * 132 + q4];
    }
}

// ---------------------------------------------------------------------------
extern "C" void kernel_launch(void* const* d_in, const int* in_sizes, int n_in,
                              void* d_out, int out_size)
{
    const float* x         = (const float*)d_in[0];
    const float* w_qkv     = (const float*)d_in[1];
    const unsigned char* m = (const unsigned char*)d_in[2];
    float* out             = (float*)d_out;

    cudaFuncSetAttribute(qkv_gemm_kernel,
                         cudaFuncAttributeMaxDynamicSharedMemorySize, GEMM_SMEM);
    cudaFuncSetAttribute(attn_kernel,
                         cudaFuncAttributeMaxDynamicSharedMemorySize, ATTN_SMEM);

    detect_mask_kernel<<<1, 1024>>>((const uint4*)m);
    maskpack_kernel<<<MWORDS / 256, 256>>>(m);
    wsplit_kernel<<<(O3C * C2 + 255) / 256, 256>>>(w_qkv);
    xsplit_kernel<<<(B_ * C2 * N_ + 255) / 256, 256>>>(x);

    dim3 gemm_grid(N_ / 128, O3C / 128, B_);   // (8, 9, 16)
    qkv_gemm_kernel<<<gemm_grid, 256, GEMM_SMEM>>>();

    dim3 attn_grid(N_ / 128, HEADS_, B_);      // (8, 6, 16)
    attn_kernel<<<attn_grid, 256, ATTN_SMEM>>>(out);
}

// round 11
// speedup vs baseline: 1.2604x; 1.2558x over previous
#include <cuda_runtime.h>
#include <cuda_bf16.h>
#include <cuda_fp16.h>
#include <math.h>
#include <float.h>
#include <stdint.h>

// Problem constants
#define B_     16
#define C_     384
#define HEADS_ 6
#define D_     64
#define N_     1024
#define O3C    1152
#define C2     (C_ / 2)      // 192

__device__ float g_qkv[B_ * O3C * N_];   // fp32 GEMM outputs
__device__ int g_mask_mode;              // 0 = uint8 bool, 1 = int32, 2 = float32
#define MWORDS (B_ * HEADS_ * N_ * (N_ / 32))
__device__ uint32_t g_mbits[MWORDS];     // bit-packed drop mask

// Pre-split W: hi/lo bf16 k-pairs, [o][c2]
__device__ uint32_t g_wh[O3C * C2];
__device__ uint32_t g_wl[O3C * C2];

// fp16-packed K and V for attention, chunk-major:
// g_kh[(bh*16+kc)*2048 + j*64 + m] = half2(K[2j][64kc+m], K[2j+1][64kc+m])
// g_vh[(bh*16+kc)*2048 + j*64 + d] = half2(V[d][64kc+2j], V[d][64kc+2j+1])
#define KHWORDS (B_ * HEADS_ * 16 * 2048)   // 3,145,728
__device__ uint32_t g_kh[KHWORDS];
__device__ uint32_t g_vh[KHWORDS];

// ---------------------------------------------------------------------------
__device__ __forceinline__ uint32_t pack_f16(float a, float b) {
    __half2 t = __floats2half2_rn(a, b);
    return *(uint32_t*)&t;
}

__device__ __forceinline__ uint32_t pack_bf16(float f0, float f1) {
    __nv_bfloat162 t = __floats2bfloat162_rn(f0, f1);
    return *(uint32_t*)&t;
}

// fp16 m16n8k16 row.col mma, f32 acc in-place
__device__ __forceinline__ void mma16f(float* c, const uint32_t* a,
                                       uint32_t b0, uint32_t b1) {
    asm volatile(
        "mma.sync.aligned.m16n8k16.row.col.f32.f16.f16.f32 "
        "{%0,%1,%2,%3}, {%4,%5,%6,%7}, {%8,%9}, {%0,%1,%2,%3};\n"
        : "+f"(c[0]), "+f"(c[1]), "+f"(c[2]), "+f"(c[3])
        : "r"(a[0]), "r"(a[1]), "r"(a[2]), "r"(a[3]), "r"(b0), "r"(b1));
}

// bf16 m16n8k16 row.col mma, f32 acc in-place (QKV GEMM)
__device__ __forceinline__ void mma16(float* c, const uint32_t* a,
                                      uint32_t b0, uint32_t b1) {
    asm volatile(
        "mma.sync.aligned.m16n8k16.row.col.f32.bf16.bf16.f32 "
        "{%0,%1,%2,%3}, {%4,%5,%6,%7}, {%8,%9}, {%0,%1,%2,%3};\n"
        : "+f"(c[0]), "+f"(c[1]), "+f"(c[2]), "+f"(c[3])
        : "r"(a[0]), "r"(a[1]), "r"(a[2]), "r"(a[3]), "r"(b0), "r"(b1));
}

__device__ __forceinline__ void cpa16(void* smem, const void* g) {
    uint32_t s = (uint32_t)__cvta_generic_to_shared(smem);
    asm volatile("cp.async.cg.shared.global [%0], [%1], 16;" :: "r"(s), "l"(g));
}

__device__ __forceinline__ float fexp2(float y) {
    y = fmaxf(y, -126.0f);
    float z = y + 12582912.0f;
    int   n = __float_as_int(z) - 0x4B400000;
    float f = y - (z - 12582912.0f);
    float p = 1.3333558146e-3f;
    p = fmaf(p, f, 9.6181291076e-3f);
    p = fmaf(p, f, 5.5504108665e-2f);
    p = fmaf(p, f, 2.4022650696e-1f);
    p = fmaf(p, f, 6.9314718056e-1f);
    p = fmaf(p, f, 1.0f);
    return __int_as_float(__float_as_int(p) + (n << 23));
}

// ---------------------------------------------------------------------------
__global__ void detect_mask_kernel(const uint4* __restrict__ m) {
    __shared__ int s_off4, s_gt1;
    if (threadIdx.x == 0) { s_off4 = 0; s_gt1 = 0; }
    __syncthreads();
    int off4 = 0, gt1 = 0;
    for (int i = threadIdx.x; i < 4096; i += blockDim.x) {
        uint4 v = m[i];
        unsigned a = v.x | v.y | v.z | v.w;
        if (a & 0xFFFFFF00u) off4 = 1;
        if (a & 0xFEFEFEFEu) gt1  = 1;
    }
    if (off4) atomicOr(&s_off4, 1);
    if (gt1)  atomicOr(&s_gt1, 1);
    __syncthreads();
    if (threadIdx.x == 0) g_mask_mode = s_gt1 ? 2 : (s_off4 ? 0 : 1);
}

// ---------------------------------------------------------------------------
#define B4(t) (((t) | ((t) >> 7) | ((t) >> 14) | ((t) >> 21)) & 0xFu)

__global__ void maskpack_kernel(const unsigned char* __restrict__ m) {
    int w = blockIdx.x * blockDim.x + threadIdx.x;
    if (w >= MWORDS) return;
    int mode = g_mask_mode;
    uint32_t bits = 0;
    if (mode == 0) {
        const uint4* p = (const uint4*)m + w * 2;
        uint4 a = p[0], b = p[1];
        bits  = B4(a.x) | (B4(a.y) << 4) | (B4(a.z) << 8)  | (B4(a.w) << 12)
              | (B4(b.x) << 16) | (B4(b.y) << 20) | (B4(b.z) << 24) | (B4(b.w) << 28);
    } else if (mode == 1) {
        const int4* p = (const int4*)m + w * 8;
        #pragma unroll
        for (int i = 0; i < 8; i++) {
            int4 v = p[i];
            bits |= (uint32_t)((v.x != 0) | ((v.y != 0) << 1) |
                               ((v.z != 0) << 2) | ((v.w != 0) << 3)) << (i * 4);
        }
    } else {
        const float4* p = (const float4*)m + w * 8;
        #pragma unroll
        for (int i = 0; i < 8; i++) {
            float4 v = p[i];
            bits |= (uint32_t)((v.x != 0.f) | ((v.y != 0.f) << 1) |
                               ((v.z != 0.f) << 2) | ((v.w != 0.f) << 3)) << (i * 4);
        }
    }
    g_mbits[w] = bits;
}

// ---------------------------------------------------------------------------
// W split (horizontal k-pairs): g_wh[o][j] = pack(w[o][2j], w[o][2j+1])
// ---------------------------------------------------------------------------
__global__ void wsplit_kernel(const float* __restrict__ w) {
    int idx = blockIdx.x * blockDim.x + threadIdx.x;
    if (idx >= O3C * C2) return;
    float2 v = *(const float2*)&w[idx * 2];
    __nv_bfloat16 h0 = __float2bfloat16(v.x);
    __nv_bfloat16 h1 = __float2bfloat16(v.y);
    g_wh[idx] = ((uint32_t)*(uint16_t*)&h1 << 16) | *(uint16_t*)&h0;
    g_wl[idx] = pack_bf16(v.x - __bfloat162float(h0),
                          v.y - __bfloat162float(h1));
}

// ---------------------------------------------------------------------------
// K fp16 pack (both reads & writes coalesced)
// ---------------------------------------------------------------------------
__global__ void khalf_kernel() {
    int idx = blockIdx.x * blockDim.x + threadIdx.x;
    if (idx >= KHWORDS) return;
    int m  = idx & 63;
    int j  = (idx >> 6) & 31;
    int kc = (idx >> 11) & 15;
    int bh = idx >> 15;
    int h = bh % HEADS_, b = bh / HEADS_;
    const float* kb = g_qkv + b * O3C * N_ + (C_ + h * D_) * N_;
    int key = kc * 64 + m;
    g_kh[idx] = pack_f16(kb[2 * j * N_ + key], kb[(2 * j + 1) * N_ + key]);
}

// ---------------------------------------------------------------------------
// V fp16 pack with smem transpose: out [j=key-pair][d]
// ---------------------------------------------------------------------------
__global__ void vhalf_kernel() {
    __shared__ float Vs[64][65];
    int blk = blockIdx.x;            // bh*16 + kc
    int kc = blk & 15;
    int bh = blk >> 4;
    int h = bh % HEADS_, b = bh / HEADS_;
    const float* vb = g_qkv + b * O3C * N_ + (2 * C_ + h * D_) * N_ + kc * 64;
    int tid = threadIdx.x;
    for (int e = tid; e < 64 * 16; e += 256) {
        int d = e >> 4, c4 = (e & 15) * 4;
        float4 v = *(const float4*)&vb[d * N_ + c4];
        Vs[d][c4] = v.x; Vs[d][c4 + 1] = v.y;
        Vs[d][c4 + 2] = v.z; Vs[d][c4 + 3] = v.w;
    }
    __syncthreads();
    uint32_t* outp = g_vh + blk * 2048;
    for (int e = tid; e < 2048; e += 256) {
        int j = e >> 6, d = e & 63;
        outp[e] = pack_f16(Vs[d][2 * j], Vs[d][2 * j + 1]);
    }
}

// ---------------------------------------------------------------------------
// QKV GEMM (R7 proven version): bf16 hi/lo 3-term, register-prefetched.
// Tile 128(o) x 128(n), KC=16. 8 warps, warp 32x64. grid (8, 9, 16)
// ---------------------------------------------------------------------------
#define WPST 12
#define XPST 136
#define NCHUNK (C_ / 16)

__global__ __launch_bounds__(256, 2) void qkv_gemm_kernel(
    const float* __restrict__ x)
{
    __shared__ uint32_t Whp[128 * WPST], Wlp[128 * WPST];
    __shared__ uint32_t Xhp[8 * XPST],   Xlp[8 * XPST];

    const int b  = blockIdx.z;
    const int o0 = blockIdx.y * 128;
    const int n0 = blockIdx.x * 128;
    const int tid  = threadIdx.x;
    const int wid  = tid >> 5;
    const int lane = tid & 31;
    const int m_base = (wid >> 1) * 32;
    const int n_base = (wid & 1) * 64;
    const int gi = lane >> 2;
    const int ti = lane & 3;

    const float* xb = x + b * C_ * N_;

    const int wo  = tid >> 1;
    const int wk2 = (tid & 1) * 4;
    const int xc2 = tid >> 5;
    const int xn  = (tid & 31) * 4;

    float acc[2][8][4];
    #pragma unroll
    for (int mf = 0; mf < 2; mf++)
        #pragma unroll
        for (int nf = 0; nf < 8; nf++)
            #pragma unroll
            for (int k = 0; k < 4; k++) acc[mf][nf][k] = 0.f;

    const uint32_t* wh_p = &g_wh[(o0 + wo) * C2 + wk2];
    const uint32_t* wl_p = &g_wl[(o0 + wo) * C2 + wk2];
    const float*    x_p  = &xb[(2 * xc2) * N_ + n0 + xn];
    uint4  whv = *(const uint4*)wh_p;
    uint4  wlv = *(const uint4*)wl_p;
    float4 xr0 = *(const float4*)x_p;
    float4 xr1 = *(const float4*)(x_p + N_);

    for (int ci = 0; ci < NCHUNK; ci++) {
        *(uint4*)&Whp[wo * WPST + wk2] = whv;
        *(uint4*)&Wlp[wo * WPST + wk2] = wlv;
        {
            float a0[4] = {xr0.x, xr0.y, xr0.z, xr0.w};
            float a1[4] = {xr1.x, xr1.y, xr1.z, xr1.w};
            uint32_t ph[4], pl[4];
            #pragma unroll
            for (int j = 0; j < 4; j++) {
                __nv_bfloat16 h0 = __float2bfloat16(a0[j]);
                __nv_bfloat16 h1 = __float2bfloat16(a1[j]);
                ph[j] = ((uint32_t)*(uint16_t*)&h1 << 16) | *(uint16_t*)&h0;
                pl[j] = pack_bf16(a0[j] - __bfloat162float(h0),
                                  a1[j] - __bfloat162float(h1));
            }
            *(uint4*)&Xhp[xc2 * XPST + xn] = make_uint4(ph[0], ph[1], ph[2], ph[3]);
            *(uint4*)&Xlp[xc2 * XPST + xn] = make_uint4(pl[0], pl[1], pl[2], pl[3]);
        }
        __syncthreads();

        if (ci + 1 < NCHUNK) {
            wh_p += 8; wl_p += 8; x_p += 16 * N_;
            whv = *(const uint4*)wh_p;
            wlv = *(const uint4*)wl_p;
            xr0 = *(const float4*)x_p;
            xr1 = *(const float4*)(x_p + N_);
        }

        uint32_t ah[2][4], al[2][4];
        #pragma unroll
        for (int mf = 0; mf < 2; mf++) {
            int r = m_base + mf * 16 + gi;
            ah[mf][0] = Whp[r * WPST + ti];
            ah[mf][1] = Whp[(r + 8) * WPST + ti];
            ah[mf][2] = Whp[r * WPST + ti + 4];
            ah[mf][3] = Whp[(r + 8) * WPST + ti + 4];
            al[mf][0] = Wlp[r * WPST + ti];
            al[mf][1] = Wlp[(r + 8) * WPST + ti];
            al[mf][2] = Wlp[r * WPST + ti + 4];
            al[mf][3] = Wlp[(r + 8) * WPST + ti + 4];
        }
        #pragma unroll
        for (int nf = 0; nf < 8; nf++) {
            int col = n_base + nf * 8 + gi;
            uint32_t bh0 = Xhp[ti * XPST + col];
            uint32_t bh1 = Xhp[(ti + 4) * XPST + col];
            uint32_t bl0 = Xlp[ti * XPST + col];
            uint32_t bl1 = Xlp[(ti + 4) * XPST + col];
            #pragma unroll
            for (int mf = 0; mf < 2; mf++) {
                mma16(acc[mf][nf], ah[mf], bh0, bh1);
                mma16(acc[mf][nf], ah[mf], bl0, bl1);
                mma16(acc[mf][nf], al[mf], bh0, bh1);
            }
        }
        __syncthreads();
    }

    float* outb = g_qkv + b * O3C * N_;
    #pragma unroll
    for (int mf = 0; mf < 2; mf++) {
        int r = o0 + m_base + mf * 16 + gi;
        #pragma unroll
        for (int nf = 0; nf < 8; nf++) {
            int nc2 = n0 + n_base + nf * 8 + 2 * ti;
            *(float2*)&outb[r * N_ + nc2]       = make_float2(acc[mf][nf][0], acc[mf][nf][1]);
            *(float2*)&outb[(r + 8) * N_ + nc2] = make_float2(acc[mf][nf][2], acc[mf][nf][3]);
        }
    }
}

// ---------------------------------------------------------------------------
// Fused flash attention, fp16 m16n8k16 mma. 128 q rows, 8 warps (16 q each).
// P stays in registers (fp16 A-frags). cp.async double-buffered fp16 K/V.
// grid = (8, 6, 16)
// ---------------------------------------------------------------------------
#define QHST 36
#define KVST 72
#define QH_OFF 0
#define K0_OFF (128 * QHST)              // 4608
#define V0_OFF (K0_OFF + 32 * KVST)      // 6912
#define K1_OFF (V0_OFF + 32 * KVST)      // 9216
#define V1_OFF (K1_OFF + 32 * KVST)      // 11520
#define SMEM_WORDS (V1_OFF + 32 * KVST)  // 13824
#define ATTN_SMEM (SMEM_WORDS * 4)       // 55296 B

__global__ __launch_bounds__(256, 2) void attn_kernel(float* __restrict__ out)
{
    extern __shared__ uint32_t As[];
    uint32_t* Qh = As;                    // [128][QHST] fp16x2 Q pairs

    const int q0 = blockIdx.x * 128;
    const int h  = blockIdx.y;
    const int b  = blockIdx.z;
    const int tid  = threadIdx.x;
    const int wid  = tid >> 5;
    const int lane = tid & 31;
    const int gi = lane >> 2;
    const int ti = lane & 3;
    const int wq = wid * 16;

    const float sc2 = rsqrtf((float)C_) * 1.4426950408889634f;
    const float NEG = -1e30f;

    const float* qb = g_qkv + (b * O3C + h * D_) * N_;
    const int bh16 = (b * HEADS_ + h) * 16;
    const int mbase = (b * HEADS_ + h) * N_ * N_;

    auto fill = [&](int sel, int kc) {
        uint32_t* Kb = As + (sel ? K1_OFF : K0_OFF);
        uint32_t* Vb = As + (sel ? V1_OFF : V0_OFF);
        const uint32_t* kg = g_kh + (bh16 + kc) * 2048;
        const uint32_t* vg = g_vh + (bh16 + kc) * 2048;
        #pragma unroll
        for (int i = 0; i < 2; i++) {
            int e = tid + i * 256;           // 0..511
            int j = e >> 4, m4 = (e & 15) * 4;
            cpa16(&Kb[j * KVST + m4], &kg[j * 64 + m4]);
            cpa16(&Vb[j * KVST + m4], &vg[j * 64 + m4]);
        }
        asm volatile("cp.async.commit_group;" ::: "memory");
    };

    fill(0, 0);

    // ---- Stage Q as fp16 pairs: Qh[q][j] = half2(Q[2j][q], Q[2j+1][q]) ----
    for (int e = tid; e < 32 * 32; e += 256) {
        int j = e >> 5, q4 = (e & 31) * 4;
        float4 va = *(const float4*)&qb[(2 * j) * N_ + q0 + q4];
        float4 vb4 = *(const float4*)&qb[(2 * j + 1) * N_ + q0 + q4];
        Qh[(q4 + 0) * QHST + j] = pack_f16(va.x, vb4.x);
        Qh[(q4 + 1) * QHST + j] = pack_f16(va.y, vb4.y);
        Qh[(q4 + 2) * QHST + j] = pack_f16(va.z, vb4.z);
        Qh[(q4 + 3) * QHST + j] = pack_f16(va.w, vb4.w);
    }
    __syncthreads();

    // ---- Q A-fragments (k16): 4 ks, 4 regs each ----
    uint32_t qa[4][4];
    #pragma unroll
    for (int ks = 0; ks < 4; ks++) {
        int r = wq + gi, c = 8 * ks + ti;
        qa[ks][0] = Qh[r * QHST + c];
        qa[ks][1] = Qh[(r + 8) * QHST + c];
        qa[ks][2] = Qh[r * QHST + c + 4];
        qa[ks][3] = Qh[(r + 8) * QHST + c + 4];
    }
    // Qh is read-only hereafter; no reuse as P (P stays in registers)

    float oa[8][4];
    #pragma unroll
    for (int nf = 0; nf < 8; nf++)
        #pragma unroll
        for (int k = 0; k < 4; k++) oa[nf][k] = 0.f;
    float m1 = NEG, m2 = NEG, l1 = 0.f, l2 = 0.f;

    const int r1g = q0 + wq + gi;
    const int mrow = (mbase + r1g * N_) >> 5;

    for (int kc = 0; kc < 16; kc++) {
        asm volatile("cp.async.wait_group 0;" ::: "memory");
        __syncthreads();

        const int widx = mrow + kc * 2;
        uint2 mwa = *(const uint2*)&g_mbits[widx];
        uint2 mwc = *(const uint2*)&g_mbits[widx + 256];

        if (kc + 1 < 16) fill((kc + 1) & 1, kc + 1);

        const uint32_t* Kc = As + ((kc & 1) ? K1_OFF : K0_OFF);
        const uint32_t* Vc = As + ((kc & 1) ? V1_OFF : V0_OFF);

        // ---- S = Q K^T : 32 mma16 ----
        float sa[8][4];
        #pragma unroll
        for (int nf = 0; nf < 8; nf++)
            #pragma unroll
            for (int k = 0; k < 4; k++) sa[nf][k] = 0.f;
        #pragma unroll
        for (int ks = 0; ks < 4; ks++) {
            const uint32_t* kr0 = &Kc[(8 * ks + ti) * KVST + gi];
            const uint32_t* kr1 = &Kc[(8 * ks + ti + 4) * KVST + gi];
            #pragma unroll
            for (int nf = 0; nf < 8; nf++) {
                mma16f(sa[nf], qa[ks], kr0[nf * 8], kr1[nf * 8]);
            }
        }

        // ---- scale + mask ----
        #pragma unroll
        for (int nf = 0; nf < 8; nf++) {
            uint32_t wa = (nf < 4) ? mwa.x : mwa.y;
            uint32_t wc = (nf < 4) ? mwc.x : mwc.y;
            int sh = (nf & 3) * 8 + 2 * ti;
            sa[nf][0] = ((wa >> sh) & 1)       ? NEG : sa[nf][0] * sc2;
            sa[nf][1] = ((wa >> (sh + 1)) & 1) ? NEG : sa[nf][1] * sc2;
            sa[nf][2] = ((wc >> sh) & 1)       ? NEG : sa[nf][2] * sc2;
            sa[nf][3] = ((wc >> (sh + 1)) & 1) ? NEG : sa[nf][3] * sc2;
        }

        // ---- online softmax; P packed straight into fp16 A-frags ----
        float mx1 = NEG, mx2 = NEG;
        #pragma unroll
        for (int nf = 0; nf < 8; nf++) {
            mx1 = fmaxf(mx1, fmaxf(sa[nf][0], sa[nf][1]));
            mx2 = fmaxf(mx2, fmaxf(sa[nf][2], sa[nf][3]));
        }
        mx1 = fmaxf(mx1, __shfl_xor_sync(0xffffffffu, mx1, 1));
        mx1 = fmaxf(mx1, __shfl_xor_sync(0xffffffffu, mx1, 2));
        mx2 = fmaxf(mx2, __shfl_xor_sync(0xffffffffu, mx2, 1));
        mx2 = fmaxf(mx2, __shfl_xor_sync(0xffffffffu, mx2, 2));
        float mn1 = fmaxf(m1, mx1), mn2 = fmaxf(m2, mx2);
        float corr1 = fexp2(m1 - mn1), corr2 = fexp2(m2 - mn2);

        uint32_t pa[4][4];
        float ls1 = 0.f, ls2 = 0.f;
        #pragma unroll
        for (int nf = 0; nf < 8; nf++) {
            float p00 = fexp2(sa[nf][0] - mn1);
            float p01 = fexp2(sa[nf][1] - mn1);
            float p10 = fexp2(sa[nf][2] - mn2);
            float p11 = fexp2(sa[nf][3] - mn2);
            ls1 += p00 + p01;
            ls2 += p10 + p11;
            int kf = nf >> 1;
            if (nf & 1) {
                pa[kf][2] = pack_f16(p00, p01);
                pa[kf][3] = pack_f16(p10, p11);
            } else {
                pa[kf][0] = pack_f16(p00, p01);
                pa[kf][1] = pack_f16(p10, p11);
            }
        }
        ls1 += __shfl_xor_sync(0xffffffffu, ls1, 1);
        ls1 += __shfl_xor_sync(0xffffffffu, ls1, 2);
        ls2 += __shfl_xor_sync(0xffffffffu, ls2, 1);
        ls2 += __shfl_xor_sync(0xffffffffu, ls2, 2);
        l1 = l1 * corr1 + ls1;
        l2 = l2 * corr2 + ls2;
        m1 = mn1; m2 = mn2;
        #pragma unroll
        for (int nf = 0; nf < 8; nf++) {
            oa[nf][0] *= corr1; oa[nf][1] *= corr1;
            oa[nf][2] *= corr2; oa[nf][3] *= corr2;
        }

        // ---- O += P V : 32 mma16, P from registers ----
        #pragma unroll
        for (int kf = 0; kf < 4; kf++) {
            const uint32_t* vr0 = &Vc[(8 * kf + ti) * KVST + gi];
            const uint32_t* vr1 = &Vc[(8 * kf + ti + 4) * KVST + gi];
            #pragma unroll
            for (int nf = 0; nf < 8; nf++) {
                mma16f(oa[nf], pa[kf], vr0[nf * 8], vr1[nf * 8]);
            }
        }
    }
    __syncthreads();

    // ---- normalize + stage to smem [d][q] for coalesced output ----
    float* Od = (float*)(As + K0_OFF);   // [64][132] staging (overlays K/V)
    float il1 = 1.0f / l1, il2 = 1.0f / l2;
    #pragma unroll
    for (int nf = 0; nf < 8; nf++) {
        int d0 = nf * 8 + 2 * ti;
        Od[d0 * 132 + wq + gi]           = oa[nf][0] * il1;
        Od[(d0 + 1) * 132 + wq + gi]     = oa[nf][1] * il1;
        Od[d0 * 132 + wq + gi + 8]       = oa[nf][2] * il2;
        Od[(d0 + 1) * 132 + wq + gi + 8] = oa[nf][3] * il2;
    }
    __syncthreads();

    float* ob = out + (b * C_ + h * D_) * N_;
    for (int e = tid; e < 64 * 32; e += 256) {
        int dd = e >> 5, q4 = (e & 31) * 4;
        *(float4*)&ob[dd * N_ + q0 + q4] = *(const float4*)&Od[dd * 132 + q4];
    }
}

// ---------------------------------------------------------------------------
extern "C" void kernel_launch(void* const* d_in, const int* in_sizes, int n_in,
                              void* d_out, int out_size)
{
    const float* x         = (const float*)d_in[0];
    const float* w_qkv     = (const float*)d_in[1];
    const unsigned char* m = (const unsigned char*)d_in[2];
    float* out             = (float*)d_out;

    cudaFuncSetAttribute(attn_kernel,
                         cudaFuncAttributeMaxDynamicSharedMemorySize, ATTN_SMEM);

    detect_mask_kernel<<<1, 1024>>>((const uint4*)m);
    maskpack_kernel<<<MWORDS / 256, 256>>>(m);
    wsplit_kernel<<<(O3C * C2 + 255) / 256, 256>>>(w_qkv);

    dim3 gemm_grid(N_ / 128, O3C / 128, B_);   // (8, 9, 16)
    qkv_gemm_kernel<<<gemm_grid, 256>>>(x);

    khalf_kernel<<<KHWORDS / 256, 256>>>();
    vhalf_kernel<<<B_ * HEADS_ * 16, 256>>>();

    dim3 attn_grid(N_ / 128, HEADS_, B_);      // (8, 6, 16)
    attn_kernel<<<attn_grid, 256, ATTN_SMEM>>>(out);
}